// round 15
// baseline (speedup 1.0000x reference)
#include <cuda_runtime.h>
#include <cstdint>

#define NB    2
#define NTT   2
#define NLG   256
#define TT    64
#define SS    256
#define NVV   4
#define FF    16
#define KNN   3
#define CUTOFF   1e-3f
#define MASKVAL  1e6f

#define NT_CTA 16          // targets per CTA
#define NTHR   128         // threads per CTA
#define ROWST  264         // row stride (floats) for dist tile AND penalty tables
#define CAP    16          // pool capacity per (t, chunk)
#define PSTR   136         // byte pool stride per t

#define BIGV 3.4e38f
#define BIGI 0x3fffffff

__device__ __forceinline__ bool lessvi(float v, int i, float w, int j) {
    return (v < w) || (v == w && i < j);
}

// exact lexicographic (value, index) top-3 insert
__device__ __forceinline__ void top3_insert_vi(float v, int s,
                                               float& d0, float& d1, float& d2,
                                               int& i0, int& i1, int& i2) {
    if (lessvi(v, s, d2, i2)) {
        if (lessvi(v, s, d1, i1)) {
            d2 = d1; i2 = i1;
            if (lessvi(v, s, d0, i0)) { d1 = d0; i1 = i0; d0 = v; i0 = s; }
            else                      { d1 = v;  i1 = s; }
        } else {
            d2 = v; i2 = s;
        }
    }
}

__device__ __forceinline__ int offmap(int s) {  // s -> padded offset
    return s + ((s >> 7) << 2);                 // s<128: s ; s>=128: s+4
}

// rare exact fallback: full 256-candidate rescan for ONE (t, nt, nv) lane.
// outlined so its registers don't inflate the hot path.
__device__ __noinline__ void full_rescan(const float* __restrict__ dt,
                                         const float* __restrict__ pn,
                                         float& r0, float& r1, float& r2,
                                         int& s0, int& s1, int& s2) {
    float a0 = BIGV, a1 = BIGV, a2 = BIGV;    // even s
    int   i0 = BIGI, i1 = BIGI, i2 = BIGI;
    float b0 = BIGV, b1 = BIGV, b2 = BIGV;    // odd s
    int   j0 = BIGI, j1 = BIGI, j2 = BIGI;
    for (int k = 0; k < 128; k++) {
        int se = k << 1;
        int oe = offmap(se);
        int oo = offmap(se + 1);
        top3_insert_vi(dt[oe] + pn[oe], se,     a0, a1, a2, i0, i1, i2);
        top3_insert_vi(dt[oo] + pn[oo], se + 1, b0, b1, b2, j0, j1, j2);
    }
    top3_insert_vi(b0, j0, a0, a1, a2, i0, i1, i2);
    top3_insert_vi(b1, j1, a0, a1, a2, i0, i1, i2);
    top3_insert_vi(b2, j2, a0, a1, a2, i0, i1, i2);
    r0 = a0; r1 = a1; r2 = a2;
    s0 = i0; s1 = i1; s2 = i2;
}

__global__ __launch_bounds__(NTHR, 8) void interp_kernel(
    const float* __restrict__ x,            // (B,NT, NL*S, NV, F)
    const void*  __restrict__ mask_raw,     // (B,NT, NL*S, NV) — dtype detected
    const float* __restrict__ dist,         // (B, NL, T, S)
    float* __restrict__ out)
{
    __shared__ float         sdist[NT_CTA * ROWST];    // 16.9 KB, shared by both nt
    __shared__ float         spen [2 * NVV * ROWST];   // 8.4 KB: [nt*4+nv][offmap(s)]
    __shared__ unsigned char pool [NT_CTA * PSTR];     // 2.1 KB survivor indices
    __shared__ unsigned char cnts [NT_CTA * 8];        // raw counts
    __shared__ int s_flags[2];

    const int bid   = blockIdx.x;
    const int tb    = bid & 3;               // which 16-target slice of 64
    const int group = bid >> 2;
    const int l     = group & 255;
    const int b     = group >> 8;            // 0..1   (no nt in bid)
    const int tid   = threadIdx.x;

    if (tid == 0) { s_flags[0] = 0; s_flags[1] = 0; }
    __syncthreads();

    // ---- mask dtype detection from first 1024 bytes ----
    {
        const uchar4* mb = (const uchar4*)mask_raw;
        int u8 = 0, f32 = 0;
        #pragma unroll
        for (int r = 0; r < 2; r++) {
            uchar4 q = mb[tid + r * NTHR];
            u8  |= (q.y == 1) | (q.z == 1) | (q.w == 1);
            f32 |= (q.x == 0x3F) | (q.y == 0x3F) | (q.z == 0x3F) | (q.w == 0x3F);
        }
        if (u8)  atomicOr(&s_flags[0], 1);
        if (f32) atomicOr(&s_flags[1], 1);
    }

    // ---- stage dist tile (16 targets x 256 sources) ONCE for both nt ----
    {
        const float4* dsrc = (const float4*)(
            dist + (((size_t)(b * NLG + l)) * TT + tb * NT_CTA) * SS);
        #pragma unroll
        for (int i = 0; i < 8; i++) {
            int g = tid + i * NTHR;
            float4 v = dsrc[g];
            int flat = g * 4;
            int t = flat >> 8;                // 0..15
            int s = flat & 255;
            *(float4*)&sdist[t * ROWST + offmap(s)] = v;
        }
    }
    __syncthreads();
    const int mkind = s_flags[0] ? 0 : (s_flags[1] ? 2 : 1);

    // ---- stage BOTH penalty tables: spen[nt*4+nv][offmap(s)] ----
    #pragma unroll
    for (int nti = 0; nti < 2; nti++) {
        const size_t moff = ((size_t)((b * NTT + nti) * NLG + l)) * SS * NVV;
        #pragma unroll
        for (int r = 0; r < 2; r++) {
            int s0 = tid + r * NTHR;          // source index 0..255
            float* pb = &spen[(nti * NVV) * ROWST + offmap(s0)];
            if (mkind == 0) {
                const uchar4* msrc = (const uchar4*)((const unsigned char*)mask_raw + moff);
                uchar4 m = msrc[s0];
                pb[0 * ROWST] = m.x ? MASKVAL : 0.0f;
                pb[1 * ROWST] = m.y ? MASKVAL : 0.0f;
                pb[2 * ROWST] = m.z ? MASKVAL : 0.0f;
                pb[3 * ROWST] = m.w ? MASKVAL : 0.0f;
            } else if (mkind == 1) {
                const int4* msrc = (const int4*)((const int*)mask_raw + moff);
                int4 m = msrc[s0];
                pb[0 * ROWST] = m.x ? MASKVAL : 0.0f;
                pb[1 * ROWST] = m.y ? MASKVAL : 0.0f;
                pb[2 * ROWST] = m.z ? MASKVAL : 0.0f;
                pb[3 * ROWST] = m.w ? MASKVAL : 0.0f;
            } else {
                const float4* msrc = (const float4*)((const float*)mask_raw + moff);
                float4 m = msrc[s0];
                pb[0 * ROWST] = m.x * MASKVAL;
                pb[1 * ROWST] = m.y * MASKVAL;
                pb[2 * ROWST] = m.z * MASKVAL;
                pb[3 * ROWST] = m.w * MASKVAL;
            }
        }
    }
    __syncthreads();

    // ============ Phase A (ONCE, nt-independent): threshold + compaction ===
    // lane owns t = tid>>3 (0..15), chunk c = tid&7; chunk covers s = c + 8j.
    const int at = tid >> 3;
    const int ac = tid & 7;
    const float* dbt = &sdist[at * ROWST];

    float q0 = BIGV, q1 = BIGV, q2 = BIGV, q3 = BIGV;
    #pragma unroll
    for (int j = 0; j < 16; j += 4) {          // s < 128
        q0 = fminf(q0, dbt[ac + 8 * (j + 0)]);
        q1 = fminf(q1, dbt[ac + 8 * (j + 1)]);
        q2 = fminf(q2, dbt[ac + 8 * (j + 2)]);
        q3 = fminf(q3, dbt[ac + 8 * (j + 3)]);
    }
    #pragma unroll
    for (int j = 16; j < 32; j += 4) {         // s >= 128 (+4 pad)
        q0 = fminf(q0, dbt[ac + 8 * (j + 0) + 4]);
        q1 = fminf(q1, dbt[ac + 8 * (j + 1) + 4]);
        q2 = fminf(q2, dbt[ac + 8 * (j + 2) + 4]);
        q3 = fminf(q3, dbt[ac + 8 * (j + 3) + 4]);
    }
    float tau = fminf(fminf(q0, q1), fminf(q2, q3));
    tau = fmaxf(tau, __shfl_xor_sync(0xffffffffu, tau, 1));
    tau = fmaxf(tau, __shfl_xor_sync(0xffffffffu, tau, 2));
    tau = fmaxf(tau, __shfl_xor_sync(0xffffffffu, tau, 4));
    // >= 8 candidates of row t are <= tau.

    {   // compaction of survivor indices into the byte pool
        unsigned char* mypool = &pool[at * PSTR + ac * CAP];
        int cnt = 0;
        #pragma unroll
        for (int j = 0; j < 16; j++) {
            int s = ac + 8 * j;
            if (dbt[s] <= tau) { if (cnt < CAP) mypool[cnt] = (unsigned char)s; cnt++; }
        }
        #pragma unroll
        for (int j = 16; j < 32; j++) {
            int s = ac + 8 * j;
            if (dbt[s + 4] <= tau) { if (cnt < CAP) mypool[cnt] = (unsigned char)s; cnt++; }
        }
        cnts[at * 8 + ac] = (unsigned char)cnt;
    }
    __syncthreads();

    // ============ Phase B: lane = (t, nt, nv); all candidates, no merges ===
    const int nv  = tid & 3;
    const int nti = (tid >> 2) & 1;
    const int t   = tid >> 3;                  // == at, tau valid for this t
    const float* dt = &sdist[t * ROWST];
    const float* pn = &spen[(nti * NVV + nv) * ROWST];

    float a0 = BIGV, a1 = BIGV, a2 = BIGV;     // even-position candidates
    int   ai0 = BIGI, ai1 = BIGI, ai2 = BIGI;
    float e0 = BIGV, e1 = BIGV, e2 = BIGV;     // odd-position candidates
    int   ei0 = BIGI, ei1 = BIGI, ei2 = BIGI;
    int ovf = 0;

    #pragma unroll
    for (int c = 0; c < 8; c++) {
        int n = cnts[t * 8 + c];
        if (n > CAP) { ovf = 1; n = CAP; }
        const unsigned char* pp = &pool[t * PSTR + c * CAP];
        int i = 0;
        for (; i + 1 < n; i += 2) {            // two independent chains
            int sA = pp[i];
            int sB = pp[i + 1];
            int oA = offmap(sA);
            int oB = offmap(sB);
            top3_insert_vi(dt[oA] + pn[oA], sA, a0, a1, a2, ai0, ai1, ai2);
            top3_insert_vi(dt[oB] + pn[oB], sB, e0, e1, e2, ei0, ei1, ei2);
        }
        if (i < n) {
            int sA = pp[i];
            int oA = offmap(sA);
            top3_insert_vi(dt[oA] + pn[oA], sA, a0, a1, a2, ai0, ai1, ai2);
        }
    }
    // merge odd into even (register-only, exact lexicographic)
    top3_insert_vi(e0, ei0, a0, a1, a2, ai0, ai1, ai2);
    top3_insert_vi(e1, ei1, a0, a1, a2, ai0, ai1, ai2);
    top3_insert_vi(e2, ei2, a0, a1, a2, ai0, ai1, ai2);

    // exactness: excluded unmasked sources have dist > tau; masked pooled
    // entries carry +1e6 > tau. a2 <= tau and no overflow => exact.
    bool flag = (ovf != 0) || (a2 > tau);
    if (flag)
        full_rescan(dt, pn, a0, a1, a2, ai0, ai1, ai2);

    // ---- weights ----
    float c0 = fmaxf(a0, CUTOFF);
    float c1 = fmaxf(a1, CUTOFF);
    float c2 = fmaxf(a2, CUTOFF);
    float w0 = 1.0f / (c0 * c0);
    float w1 = 1.0f / (c1 * c1);
    float w2 = 1.0f / (c2 * c2);
    float inv = 1.0f / (w0 + w1 + w2);
    w0 *= inv; w1 *= inv; w2 *= inv;

    // ---- gather + blend: this lane writes all 4 float4s of its (t,nt,nv) ----
    const int tg = t + tb * NT_CTA;            // global target 0..63
    const float* xb = x + ((size_t)((b * NTT + nti) * NLG + l)) * SS * NVV * FF;
    const float4* xp0 = (const float4*)(xb + ((size_t)ai0 * NVV + nv) * FF);
    const float4* xp1 = (const float4*)(xb + ((size_t)ai1 * NVV + nv) * FF);
    const float4* xp2 = (const float4*)(xb + ((size_t)ai2 * NVV + nv) * FF);

    const size_t row = (size_t)((b * NTT + nti) * (NLG * TT)) + (size_t)l * TT + tg;
    float4* op = (float4*)(out + (row * NVV + nv) * FF);

    #pragma unroll
    for (int j = 0; j < 4; j++) {
        float4 va = xp0[j], vb = xp1[j], vc = xp2[j];
        float4 rr;
        rr.x = w0 * va.x + w1 * vb.x + w2 * vc.x;
        rr.y = w0 * va.y + w1 * vb.y + w2 * vc.y;
        rr.z = w0 * va.z + w1 * vb.z + w2 * vc.z;
        rr.w = w0 * va.w + w1 * vb.w + w2 * vc.w;
        op[j] = rr;
    }

    // ---- dist_vals output ----
    const size_t XSZ = (size_t)NB * NTT * NLG * TT * NVV * FF;  // 4,194,304
    size_t dbaseo = XSZ + (row * KNN) * NVV + nv;
    out[dbaseo]           = c0;
    out[dbaseo + NVV]     = c1;
    out[dbaseo + 2 * NVV] = c2;
}

extern "C" void kernel_launch(void* const* d_in, const int* in_sizes, int n_in,
                              void* d_out, int out_size) {
    const float* x    = (const float*)d_in[0];
    const void*  mask = (const void*)d_in[1];
    const float* dist = (const float*)d_in[2];
    float*       out  = (float*)d_out;

    interp_kernel<<<NB * NLG * 4, NTHR>>>(x, mask, dist, out);
}